// round 9
// baseline (speedup 1.0000x reference)
#include <cuda_runtime.h>
#include <math.h>

#define BB    64
#define NN    2048
#define DIM   768
#define POOL  1024
#define LEN   16
#define ROW   2080          // 2*LEN + NN
#define NCHUNK 32
#define CH    64            // NN / NCHUNK
#define D4    192           // DIM / 4
#define QSTR  193           // smem query row stride in float4
#define PBLK  64            // sim prompt-blocks (16 prompts each)

// ---------------- scratch (device globals; only referenced in device code) --
__device__ __align__(16) float g_part[NCHUNK * BB * DIM];
__device__ __align__(16) float g_xnorm[BB * DIM];
__device__ __align__(16) float g_resq[BB * DIM];
__device__ float g_c1v[PBLK * BB];
__device__ int   g_c1i[PBLK * BB];
__device__ float g_c2v[PBLK * BB];
__device__ int   g_c2i[PBLK * BB];
__device__ int   g_idx[BB];
__device__ float g_maxsim[BB];
__device__ int   g_cnt_mean[BB];      // zero-init; self-resetting
__device__ int   g_cnt_sim[2];        // zero-init; self-resetting

__device__ __forceinline__ float warp_sum(float v) {
    #pragma unroll
    for (int o = 16; o > 0; o >>= 1) v += __shfl_xor_sync(0xffffffffu, v, o);
    return v;
}

// butterfly argmax (tie -> lowest index); all lanes end with the global best
__device__ __forceinline__ void warp_argmax(float& v, int& i) {
    #pragma unroll
    for (int o = 16; o > 0; o >>= 1) {
        float ov = __shfl_xor_sync(0xffffffffu, v, o);
        int   oi = __shfl_xor_sync(0xffffffffu, i, o);
        if (ov > v || (ov == v && oi < i)) { v = ov; i = oi; }
    }
}

// reduce the 64 per-block candidates for batch b (one warp, all lanes get best)
__device__ __forceinline__ void reduce_cand(const float* cv, const int* ci,
                                            int b, int lane, float& v, int& i) {
    float va = cv[lane * BB + b];        int ia = ci[lane * BB + b];
    float vb = cv[(lane + 32) * BB + b]; int ib = ci[(lane + 32) * BB + b];
    if (vb > va || (vb == va && ib < ia)) { va = vb; ia = ib; }
    v = va; i = ia;
    warp_argmax(v, i);
}

// ---------------------------------------------------------------------------
// K1: stream x_embed -> out[:, 32:, :] accumulating partial sums; the LAST
// chunk-block per batch b finalizes mean + l2norm -> g_xnorm (fused k_xnorm).
// grid (BB, NCHUNK), 192 threads.
// ---------------------------------------------------------------------------
__global__ void k_mean_copy(const float* __restrict__ x, float* __restrict__ out) {
    const int t = threadIdx.x;            // 0..191
    const int b = blockIdx.x;
    const int z = blockIdx.y;

    const float4* src = reinterpret_cast<const float4*>(
        x + ((size_t)b * NN + (size_t)z * CH) * DIM) + t;
    float4* dst = reinterpret_cast<float4*>(
        out + ((size_t)b * ROW + 2 * LEN + (size_t)z * CH) * DIM) + t;

    float4 s = make_float4(0.f, 0.f, 0.f, 0.f);
    for (int n0 = 0; n0 < CH; n0 += 8) {
        float4 v[8];
        #pragma unroll
        for (int k = 0; k < 8; k++)
            v[k] = __ldcs(src + (size_t)(n0 + k) * D4);
        #pragma unroll
        for (int k = 0; k < 8; k++) {
            s.x += v[k].x; s.y += v[k].y; s.z += v[k].z; s.w += v[k].w;
            __stcs(dst + (size_t)(n0 + k) * D4, v[k]);
        }
    }
    reinterpret_cast<float4*>(g_part)[((size_t)z * BB + b) * D4 + t] = s;

    // --- last-block-per-b completion: fused xnorm ---
    __shared__ int s_last;
    __threadfence();
    __syncthreads();
    if (t == 0) {
        int old = atomicAdd(&g_cnt_mean[b], 1);
        s_last = (old == NCHUNK - 1);
    }
    __syncthreads();
    if (!s_last) return;
    __threadfence();                      // acquire side

    const int w = t >> 5, lane = t & 31;
    float4 acc = make_float4(0.f, 0.f, 0.f, 0.f);
    #pragma unroll
    for (int z2 = 0; z2 < NCHUNK; z2++) {
        float4 p = reinterpret_cast<const float4*>(g_part)[((size_t)z2 * BB + b) * D4 + t];
        acc.x += p.x; acc.y += p.y; acc.z += p.z; acc.w += p.w;
    }
    const float inv = 1.0f / (float)NN;
    float4 v = make_float4(acc.x * inv, acc.y * inv, acc.z * inv, acc.w * inv);

    float ss = v.x * v.x + v.y * v.y + v.z * v.z + v.w * v.w;
    ss = warp_sum(ss);
    __shared__ float sm[6];
    __shared__ float s_rinv;
    if (lane == 0) sm[w] = ss;
    __syncthreads();
    if (t == 0) {
        float tot = 0.f;
        #pragma unroll
        for (int i = 0; i < 6; i++) tot += sm[i];
        s_rinv = 1.0f / sqrtf(fmaxf(tot, 1e-12f));
        g_cnt_mean[b] = 0;                // reset for next graph replay
    }
    __syncthreads();
    const float rinv = s_rinv;
    reinterpret_cast<float4*>(g_xnorm + (size_t)b * DIM)[t] =
        make_float4(v.x * rinv, v.y * rinv, v.z * rinv, v.w * rinv);
}

// ---------------------------------------------------------------------------
// K2/K3: tiled sim GEMM, fused key normalization + per-block argmax.
// grid (PBLK, 2), 256 threads (8 warps, 2 prompts/warp, 32 queries/tile).
// which=0: additionally, the LAST pblock per bt-tile reduces candidates to
// g_idx/g_maxsim and builds g_resq for its 32 batches (fused k_resq).
// ---------------------------------------------------------------------------
__global__ void k_sim(const float* __restrict__ keys,
                      const float* __restrict__ pk, int which) {
    const int pb = blockIdx.x;
    const int bt = blockIdx.y;
    const int t = threadIdx.x;
    const int w = t >> 5, lane = t & 31;

    extern __shared__ float4 sq[];        // [32][QSTR] float4
    const float* qbase = which ? g_resq : g_xnorm;

    for (int i = t; i < 32 * D4; i += 256) {
        const int r = i / D4, c = i % D4;
        sq[r * QSTR + c] =
            reinterpret_cast<const float4*>(qbase + (size_t)(bt * 32 + r) * DIM)[c];
    }
    __syncthreads();

    const int p0 = pb * 16 + w * 2;
    const float4* k0 = reinterpret_cast<const float4*>(keys + (size_t)p0 * DIM);
    const float4* k1 = k0 + D4;

    // key norms (coalesced pass + warp reduce)
    float s0 = 0.f, s1 = 0.f;
    #pragma unroll
    for (int jj = 0; jj < 6; jj++) {
        float4 a = k0[lane + 32 * jj];
        s0 += a.x * a.x + a.y * a.y + a.z * a.z + a.w * a.w;
        float4 c = k1[lane + 32 * jj];
        s1 += c.x * c.x + c.y * c.y + c.z * c.z + c.w * c.w;
    }
    s0 = warp_sum(s0); s1 = warp_sum(s1);
    const float r0 = 1.0f / sqrtf(fmaxf(s0, 1e-12f));
    const float r1 = 1.0f / sqrtf(fmaxf(s1, 1e-12f));

    // lane owns query row (bt*32 + lane); keys via uniform (broadcast) loads
    const float4* q = sq + (size_t)lane * QSTR;
    float a0 = 0.f, a1 = 0.f, b0 = 0.f, b1 = 0.f;
    #pragma unroll 4
    for (int j = 0; j < D4; j++) {
        float4 ka = k0[j];
        float4 kb = k1[j];
        float4 qq = q[j];
        a0 += ka.x * qq.x + ka.y * qq.y;
        a1 += ka.z * qq.z + ka.w * qq.w;
        b0 += kb.x * qq.x + kb.y * qq.y;
        b1 += kb.z * qq.z + kb.w * qq.w;
    }
    const float v0 = r0 * (a0 + a1);
    const float v1 = r1 * (b0 + b1);

    float bv = v0; int bi = p0;
    if (v1 > v0) { bv = v1; bi = p0 + 1; }

    __shared__ float cvs[8][32];
    __shared__ int   cis[8][32];
    cvs[w][lane] = bv; cis[w][lane] = bi;
    __syncthreads();
    if (w == 0) {
        float best = cvs[0][lane]; int besti = cis[0][lane];
        #pragma unroll
        for (int i = 1; i < 8; i++) {
            float ov = cvs[i][lane]; int oi = cis[i][lane];
            if (ov > best || (ov == best && oi < besti)) { best = ov; besti = oi; }
        }
        const int b = bt * 32 + lane;
        if (which) { g_c2v[pb * BB + b] = best; g_c2i[pb * BB + b] = besti; }
        else       { g_c1v[pb * BB + b] = best; g_c1i[pb * BB + b] = besti; }
    }

    if (which) return;

    // --- last-pblock-per-bt completion: fused resq build ---
    __shared__ int s_last;
    __threadfence();
    __syncthreads();
    if (t == 0) {
        int old = atomicAdd(&g_cnt_sim[bt], 1);
        s_last = (old == PBLK - 1);
    }
    __syncthreads();
    if (!s_last) return;
    __threadfence();

    __shared__ int s_idx[32];
    // 8 warps x 4 batches each: reduce 64 candidates per batch
    #pragma unroll
    for (int k = 0; k < 4; k++) {
        const int b = bt * 32 + w * 4 + k;
        float v; int i;
        reduce_cand(g_c1v, g_c1i, b, lane, v, i);
        if (lane == 0) {
            g_idx[b] = i; g_maxsim[b] = v;
            s_idx[w * 4 + k] = i;
        }
    }
    if (t == 0) g_cnt_sim[bt] = 0;        // reset for next replay
    __syncthreads();
    // build resq rows for this tile's 32 batches
    for (int i = t; i < 32 * D4; i += 256) {
        const int r = i / D4, c = i % D4;
        const int b = bt * 32 + r;
        float4 a  = reinterpret_cast<const float4*>(pk + (size_t)s_idx[r] * DIM)[c];
        float4 xn = reinterpret_cast<const float4*>(g_xnorm + (size_t)b * DIM)[c];
        reinterpret_cast<float4*>(g_resq + (size_t)b * DIM)[c] =
            make_float4(a.x - xn.x, a.y - xn.y, a.z - xn.z, a.w - xn.w);
    }
}

// ---------------------------------------------------------------------------
// K4: reduce level-2 candidates, gather winning prompts, write scalar loss.
// grid BB, 256 threads.
// ---------------------------------------------------------------------------
__global__ void k_gather(const float* __restrict__ prompt,
                         const float* __restrict__ rprompt,
                         float* __restrict__ out,
                         long long out_size) {
    const int b = blockIdx.x;
    const int t = threadIdx.x;            // 256 threads
    __shared__ int s_ridx;
    if (t < 32) {
        float v; int i;
        reduce_cand(g_c2v, g_c2i, b, t, v, i);
        if (t == 0) s_ridx = i;
    }
    __syncthreads();
    const int idx  = g_idx[b];
    const int ridx = s_ridx;

    const float4* s1 = reinterpret_cast<const float4*>(rprompt + (size_t)ridx * LEN * DIM);
    const float4* s2 = reinterpret_cast<const float4*>(prompt  + (size_t)idx  * LEN * DIM);
    float4* dst = reinterpret_cast<float4*>(out + (size_t)b * ROW * DIM);

    const int SEG = LEN * DIM / 4;        // 3072
    #pragma unroll 4
    for (int i = t; i < SEG; i += 256) dst[i] = s1[i];
    #pragma unroll 4
    for (int i = t; i < SEG; i += 256) dst[SEG + i] = s2[i];

    // scalar: block 0, threads 0..63 each reduce batch t's level-2 candidates
    if (b == 0) {
        __shared__ float psum[64];
        if (t < 64) {
            float v = g_c2v[t]; int i = g_c2i[t];
            #pragma unroll 8
            for (int pbk = 1; pbk < PBLK; pbk++) {
                float ov = g_c2v[pbk * BB + t]; int oi = g_c2i[pbk * BB + t];
                if (ov > v || (ov == v && oi < i)) { v = ov; i = oi; }
            }
            psum[t] = g_maxsim[t] + v;
        }
        __syncthreads();
        if (t == 0) {
            float s = 0.f;
            #pragma unroll
            for (int i = 0; i < 64; i++) s += psum[i];
            s *= (1.0f / (float)BB);
            const size_t np = (size_t)BB * ROW * DIM;
            if ((size_t)out_size > np) out[(size_t)out_size - 1] = s;
        }
    }
}

// ---------------------------------------------------------------------------
extern "C" void kernel_launch(void* const* d_in, const int* in_sizes, int n_in,
                              void* d_out, int out_size) {
    const float* x       = (const float*)d_in[0];
    const float* prompt  = (const float*)d_in[1];
    const float* pk      = (const float*)d_in[2];
    const float* rprompt = (const float*)d_in[3];
    const float* rpk     = (const float*)d_in[4];
    float* out = (float*)d_out;

    const int SIM_SMEM = 32 * QSTR * 16;  // 98816 bytes
    static int attr_done = 0;
    if (!attr_done) {
        cudaFuncSetAttribute(k_sim, cudaFuncAttributeMaxDynamicSharedMemorySize, SIM_SMEM);
        attr_done = 1;
    }

    k_mean_copy<<<dim3(BB, NCHUNK), D4>>>(x, out);
    k_sim<<<dim3(PBLK, 2), 256, SIM_SMEM>>>(pk, pk, 0);
    k_sim<<<dim3(PBLK, 2), 256, SIM_SMEM>>>(rpk, pk, 1);
    k_gather<<<BB, 256>>>(prompt, rprompt, out, (long long)out_size);
}

// round 10
// speedup vs baseline: 1.0200x; 1.0200x over previous
#include <cuda_runtime.h>
#include <math.h>

#define BB    64
#define NN    2048
#define DIM   768
#define POOL  1024
#define LEN   16
#define ROW   2080          // 2*LEN + NN
#define NCHUNK 32
#define CH    64            // NN / NCHUNK
#define D4    192           // DIM / 4
#define QSTR  193           // smem query row stride in float4
#define PBLK  64            // sim prompt-blocks (16 prompts each)

// ---------------- scratch (device globals; only referenced in device code) --
__device__ __align__(16) float g_part[NCHUNK * BB * DIM];
__device__ __align__(16) float g_xnorm[BB * DIM];
__device__ __align__(16) float g_resq[BB * DIM];
__device__ float g_c1v[PBLK * BB];
__device__ int   g_c1i[PBLK * BB];
__device__ float g_c2v[PBLK * BB];
__device__ int   g_c2i[PBLK * BB];
__device__ int   g_idx[BB];
__device__ float g_maxsim[BB];
__device__ int   g_cnt_mean[BB];      // zero-init; self-resetting
__device__ int   g_cnt_sim[2];        // zero-init; self-resetting

__device__ __forceinline__ float warp_sum(float v) {
    #pragma unroll
    for (int o = 16; o > 0; o >>= 1) v += __shfl_xor_sync(0xffffffffu, v, o);
    return v;
}

// butterfly argmax (tie -> lowest index); all lanes end with the global best
__device__ __forceinline__ void warp_argmax(float& v, int& i) {
    #pragma unroll
    for (int o = 16; o > 0; o >>= 1) {
        float ov = __shfl_xor_sync(0xffffffffu, v, o);
        int   oi = __shfl_xor_sync(0xffffffffu, i, o);
        if (ov > v || (ov == v && oi < i)) { v = ov; i = oi; }
    }
}

// reduce the 64 per-block candidates for batch b (one warp, all lanes get best)
__device__ __forceinline__ void reduce_cand(const float* cv, const int* ci,
                                            int b, int lane, float& v, int& i) {
    float va = cv[lane * BB + b];        int ia = ci[lane * BB + b];
    float vb = cv[(lane + 32) * BB + b]; int ib = ci[(lane + 32) * BB + b];
    if (vb > va || (vb == va && ib < ia)) { va = vb; ia = ib; }
    v = va; i = ia;
    warp_argmax(v, i);
}

// ---------------------------------------------------------------------------
// K1: stream x_embed -> out[:, 32:, :] accumulating partial sums; the LAST
// chunk-block per batch b finalizes mean + l2norm -> g_xnorm (fused k_xnorm).
// grid (BB, NCHUNK), 192 threads.
// ---------------------------------------------------------------------------
__global__ void k_mean_copy(const float* __restrict__ x, float* __restrict__ out) {
    const int t = threadIdx.x;            // 0..191
    const int b = blockIdx.x;
    const int z = blockIdx.y;

    const float4* src = reinterpret_cast<const float4*>(
        x + ((size_t)b * NN + (size_t)z * CH) * DIM) + t;
    float4* dst = reinterpret_cast<float4*>(
        out + ((size_t)b * ROW + 2 * LEN + (size_t)z * CH) * DIM) + t;

    float4 s = make_float4(0.f, 0.f, 0.f, 0.f);
    for (int n0 = 0; n0 < CH; n0 += 8) {
        float4 v[8];
        #pragma unroll
        for (int k = 0; k < 8; k++)
            v[k] = __ldcs(src + (size_t)(n0 + k) * D4);
        #pragma unroll
        for (int k = 0; k < 8; k++) {
            s.x += v[k].x; s.y += v[k].y; s.z += v[k].z; s.w += v[k].w;
            __stcs(dst + (size_t)(n0 + k) * D4, v[k]);
        }
    }
    reinterpret_cast<float4*>(g_part)[((size_t)z * BB + b) * D4 + t] = s;

    // --- last-block-per-b completion: fused xnorm ---
    __shared__ int s_last;
    __threadfence();
    __syncthreads();
    if (t == 0) {
        int old = atomicAdd(&g_cnt_mean[b], 1);
        s_last = (old == NCHUNK - 1);
    }
    __syncthreads();
    if (!s_last) return;
    __threadfence();                      // acquire side

    const int w = t >> 5, lane = t & 31;
    float4 acc = make_float4(0.f, 0.f, 0.f, 0.f);
    #pragma unroll
    for (int z2 = 0; z2 < NCHUNK; z2++) {
        float4 p = reinterpret_cast<const float4*>(g_part)[((size_t)z2 * BB + b) * D4 + t];
        acc.x += p.x; acc.y += p.y; acc.z += p.z; acc.w += p.w;
    }
    const float inv = 1.0f / (float)NN;
    float4 v = make_float4(acc.x * inv, acc.y * inv, acc.z * inv, acc.w * inv);

    float ss = v.x * v.x + v.y * v.y + v.z * v.z + v.w * v.w;
    ss = warp_sum(ss);
    __shared__ float sm[6];
    __shared__ float s_rinv;
    if (lane == 0) sm[w] = ss;
    __syncthreads();
    if (t == 0) {
        float tot = 0.f;
        #pragma unroll
        for (int i = 0; i < 6; i++) tot += sm[i];
        s_rinv = 1.0f / sqrtf(fmaxf(tot, 1e-12f));
        g_cnt_mean[b] = 0;                // reset for next graph replay
    }
    __syncthreads();
    const float rinv = s_rinv;
    reinterpret_cast<float4*>(g_xnorm + (size_t)b * DIM)[t] =
        make_float4(v.x * rinv, v.y * rinv, v.z * rinv, v.w * rinv);
}

// ---------------------------------------------------------------------------
// K2/K3: tiled sim GEMM, fused key normalization + per-block argmax.
// grid (PBLK, 2), 256 threads (8 warps, 2 prompts/warp, 32 queries/tile).
// which=0: additionally, the LAST pblock per bt-tile reduces candidates to
// g_idx/g_maxsim and builds g_resq for its 32 batches (fused k_resq).
// ---------------------------------------------------------------------------
__global__ void k_sim(const float* __restrict__ keys,
                      const float* __restrict__ pk, int which) {
    const int pb = blockIdx.x;
    const int bt = blockIdx.y;
    const int t = threadIdx.x;
    const int w = t >> 5, lane = t & 31;

    extern __shared__ float4 sq[];        // [32][QSTR] float4
    const float* qbase = which ? g_resq : g_xnorm;

    for (int i = t; i < 32 * D4; i += 256) {
        const int r = i / D4, c = i % D4;
        sq[r * QSTR + c] =
            reinterpret_cast<const float4*>(qbase + (size_t)(bt * 32 + r) * DIM)[c];
    }
    __syncthreads();

    const int p0 = pb * 16 + w * 2;
    const float4* k0 = reinterpret_cast<const float4*>(keys + (size_t)p0 * DIM);
    const float4* k1 = k0 + D4;

    // key norms (coalesced pass + warp reduce)
    float s0 = 0.f, s1 = 0.f;
    #pragma unroll
    for (int jj = 0; jj < 6; jj++) {
        float4 a = k0[lane + 32 * jj];
        s0 += a.x * a.x + a.y * a.y + a.z * a.z + a.w * a.w;
        float4 c = k1[lane + 32 * jj];
        s1 += c.x * c.x + c.y * c.y + c.z * c.z + c.w * c.w;
    }
    s0 = warp_sum(s0); s1 = warp_sum(s1);
    const float r0 = 1.0f / sqrtf(fmaxf(s0, 1e-12f));
    const float r1 = 1.0f / sqrtf(fmaxf(s1, 1e-12f));

    // lane owns query row (bt*32 + lane); keys via uniform (broadcast) loads
    const float4* q = sq + (size_t)lane * QSTR;
    float a0 = 0.f, a1 = 0.f, b0 = 0.f, b1 = 0.f;
    #pragma unroll 4
    for (int j = 0; j < D4; j++) {
        float4 ka = k0[j];
        float4 kb = k1[j];
        float4 qq = q[j];
        a0 += ka.x * qq.x + ka.y * qq.y;
        a1 += ka.z * qq.z + ka.w * qq.w;
        b0 += kb.x * qq.x + kb.y * qq.y;
        b1 += kb.z * qq.z + kb.w * qq.w;
    }
    const float v0 = r0 * (a0 + a1);
    const float v1 = r1 * (b0 + b1);

    float bv = v0; int bi = p0;
    if (v1 > v0) { bv = v1; bi = p0 + 1; }

    __shared__ float cvs[8][32];
    __shared__ int   cis[8][32];
    cvs[w][lane] = bv; cis[w][lane] = bi;
    __syncthreads();
    if (w == 0) {
        float best = cvs[0][lane]; int besti = cis[0][lane];
        #pragma unroll
        for (int i = 1; i < 8; i++) {
            float ov = cvs[i][lane]; int oi = cis[i][lane];
            if (ov > best || (ov == best && oi < besti)) { best = ov; besti = oi; }
        }
        const int b = bt * 32 + lane;
        if (which) { g_c2v[pb * BB + b] = best; g_c2i[pb * BB + b] = besti; }
        else       { g_c1v[pb * BB + b] = best; g_c1i[pb * BB + b] = besti; }
    }

    if (which) return;

    // --- last-pblock-per-bt completion: fused resq build ---
    __shared__ int s_last;
    __threadfence();
    __syncthreads();
    if (t == 0) {
        int old = atomicAdd(&g_cnt_sim[bt], 1);
        s_last = (old == PBLK - 1);
    }
    __syncthreads();
    if (!s_last) return;
    __threadfence();

    __shared__ int s_idx[32];
    // 8 warps x 4 batches each: reduce 64 candidates per batch
    #pragma unroll
    for (int k = 0; k < 4; k++) {
        const int b = bt * 32 + w * 4 + k;
        float v; int i;
        reduce_cand(g_c1v, g_c1i, b, lane, v, i);
        if (lane == 0) {
            g_idx[b] = i; g_maxsim[b] = v;
            s_idx[w * 4 + k] = i;
        }
    }
    if (t == 0) g_cnt_sim[bt] = 0;        // reset for next replay
    __syncthreads();
    // build resq rows for this tile's 32 batches
    for (int i = t; i < 32 * D4; i += 256) {
        const int r = i / D4, c = i % D4;
        const int b = bt * 32 + r;
        float4 a  = reinterpret_cast<const float4*>(pk + (size_t)s_idx[r] * DIM)[c];
        float4 xn = reinterpret_cast<const float4*>(g_xnorm + (size_t)b * DIM)[c];
        reinterpret_cast<float4*>(g_resq + (size_t)b * DIM)[c] =
            make_float4(a.x - xn.x, a.y - xn.y, a.z - xn.z, a.w - xn.w);
    }
}

// ---------------------------------------------------------------------------
// K4: reduce level-2 candidates, gather winning prompts, write scalar loss.
// grid BB, 256 threads.
// ---------------------------------------------------------------------------
__global__ void k_gather(const float* __restrict__ prompt,
                         const float* __restrict__ rprompt,
                         float* __restrict__ out,
                         long long out_size) {
    const int b = blockIdx.x;
    const int t = threadIdx.x;            // 256 threads
    __shared__ int s_ridx;
    if (t < 32) {
        float v; int i;
        reduce_cand(g_c2v, g_c2i, b, t, v, i);
        if (t == 0) s_ridx = i;
    }
    __syncthreads();
    const int idx  = g_idx[b];
    const int ridx = s_ridx;

    const float4* s1 = reinterpret_cast<const float4*>(rprompt + (size_t)ridx * LEN * DIM);
    const float4* s2 = reinterpret_cast<const float4*>(prompt  + (size_t)idx  * LEN * DIM);
    float4* dst = reinterpret_cast<float4*>(out + (size_t)b * ROW * DIM);

    const int SEG = LEN * DIM / 4;        // 3072
    #pragma unroll 4
    for (int i = t; i < SEG; i += 256) dst[i] = s1[i];
    #pragma unroll 4
    for (int i = t; i < SEG; i += 256) dst[SEG + i] = s2[i];

    // scalar: block 0, threads 0..63 each reduce batch t's level-2 candidates
    if (b == 0) {
        __shared__ float psum[64];
        if (t < 64) {
            float v = g_c2v[t]; int i = g_c2i[t];
            #pragma unroll 8
            for (int pbk = 1; pbk < PBLK; pbk++) {
                float ov = g_c2v[pbk * BB + t]; int oi = g_c2i[pbk * BB + t];
                if (ov > v || (ov == v && oi < i)) { v = ov; i = oi; }
            }
            psum[t] = g_maxsim[t] + v;
        }
        __syncthreads();
        if (t == 0) {
            float s = 0.f;
            #pragma unroll
            for (int i = 0; i < 64; i++) s += psum[i];
            s *= (1.0f / (float)BB);
            const size_t np = (size_t)BB * ROW * DIM;
            if ((size_t)out_size > np) out[(size_t)out_size - 1] = s;
        }
    }
}

// ---------------------------------------------------------------------------
extern "C" void kernel_launch(void* const* d_in, const int* in_sizes, int n_in,
                              void* d_out, int out_size) {
    const float* x       = (const float*)d_in[0];
    const float* prompt  = (const float*)d_in[1];
    const float* pk      = (const float*)d_in[2];
    const float* rprompt = (const float*)d_in[3];
    const float* rpk     = (const float*)d_in[4];
    float* out = (float*)d_out;

    const int SIM_SMEM = 32 * QSTR * 16;  // 98816 bytes
    static int attr_done = 0;
    if (!attr_done) {
        cudaFuncSetAttribute(k_sim, cudaFuncAttributeMaxDynamicSharedMemorySize, SIM_SMEM);
        attr_done = 1;
    }

    k_mean_copy<<<dim3(BB, NCHUNK), D4>>>(x, out);
    k_sim<<<dim3(PBLK, 2), 256, SIM_SMEM>>>(pk, pk, 0);
    k_sim<<<dim3(PBLK, 2), 256, SIM_SMEM>>>(rpk, pk, 1);
    k_gather<<<BB, 256>>>(prompt, rprompt, out, (long long)out_size);
}

// round 11
// speedup vs baseline: 1.0212x; 1.0012x over previous
#include <cuda_runtime.h>
#include <math.h>

#define BB    64
#define NN    2048
#define DIM   768
#define POOL  1024
#define LEN   16
#define ROW   2080          // 2*LEN + NN
#define NCHUNK 32
#define CH    64            // NN / NCHUNK
#define D4    192           // DIM / 4
#define QSTR  193           // smem query row stride in float4
#define PBLK  64            // sim prompt-blocks (16 prompts each)
#define CHAIN_BLOCKS 128    // PBLK * 2 tiles

// ---------------- scratch (device globals; only referenced in device code) --
__device__ __align__(16) float g_part[NCHUNK * BB * DIM];
__device__ __align__(16) float g_xnorm[BB * DIM];
__device__ __align__(16) float g_resq[BB * DIM];
__device__ float g_c1v[PBLK * BB];
__device__ int   g_c1i[PBLK * BB];
__device__ float g_c2v[PBLK * BB];
__device__ int   g_c2i[PBLK * BB];
__device__ int   g_idx[BB];
__device__ float g_maxsim[BB];
__device__ int   g_cnt_mean[BB];      // zero-init; self-resetting
__device__ int   g_bar[4];            // chain grid barriers; self-resetting

__device__ __forceinline__ float warp_sum(float v) {
    #pragma unroll
    for (int o = 16; o > 0; o >>= 1) v += __shfl_xor_sync(0xffffffffu, v, o);
    return v;
}

__device__ __forceinline__ void warp_argmax(float& v, int& i) {
    #pragma unroll
    for (int o = 16; o > 0; o >>= 1) {
        float ov = __shfl_xor_sync(0xffffffffu, v, o);
        int   oi = __shfl_xor_sync(0xffffffffu, i, o);
        if (ov > v || (ov == v && oi < i)) { v = ov; i = oi; }
    }
}

// reduce the 64 per-block candidates for batch b (one warp, all lanes get best)
__device__ __forceinline__ void reduce_cand(const float* cv, const int* ci,
                                            int b, int lane, float& v, int& i) {
    float va = cv[lane * BB + b];        int ia = ci[lane * BB + b];
    float vb = cv[(lane + 32) * BB + b]; int ib = ci[(lane + 32) * BB + b];
    if (vb > va || (vb == va && ib < ia)) { va = vb; ia = ib; }
    v = va; i = ia;
    warp_argmax(v, i);
}

// grid barrier: all CHAIN_BLOCKS blocks co-resident (1 block/SM), so spinning
// is deadlock-free. Counters reset at exit barrier by the last arriver.
__device__ __forceinline__ void grid_bar(int id) {
    __syncthreads();
    if (threadIdx.x == 0) {
        __threadfence();
        atomicAdd(&g_bar[id], 1);
        while (*(volatile int*)&g_bar[id] < CHAIN_BLOCKS) { }
        __threadfence();
    }
    __syncthreads();
}

// ---------------------------------------------------------------------------
// K1: stream x_embed -> out[:, 32:, :] accumulating partial sums; the LAST
// chunk-block per batch b finalizes mean + l2norm -> g_xnorm.
// grid (BB, NCHUNK), 192 threads.
// ---------------------------------------------------------------------------
__global__ void k_mean_copy(const float* __restrict__ x, float* __restrict__ out) {
    const int t = threadIdx.x;            // 0..191
    const int b = blockIdx.x;
    const int z = blockIdx.y;

    const float4* src = reinterpret_cast<const float4*>(
        x + ((size_t)b * NN + (size_t)z * CH) * DIM) + t;
    float4* dst = reinterpret_cast<float4*>(
        out + ((size_t)b * ROW + 2 * LEN + (size_t)z * CH) * DIM) + t;

    float4 s = make_float4(0.f, 0.f, 0.f, 0.f);
    for (int n0 = 0; n0 < CH; n0 += 8) {
        float4 v[8];
        #pragma unroll
        for (int k = 0; k < 8; k++)
            v[k] = __ldcs(src + (size_t)(n0 + k) * D4);
        #pragma unroll
        for (int k = 0; k < 8; k++) {
            s.x += v[k].x; s.y += v[k].y; s.z += v[k].z; s.w += v[k].w;
            __stcs(dst + (size_t)(n0 + k) * D4, v[k]);
        }
    }
    reinterpret_cast<float4*>(g_part)[((size_t)z * BB + b) * D4 + t] = s;

    __shared__ int s_last;
    __threadfence();
    __syncthreads();
    if (t == 0) {
        int old = atomicAdd(&g_cnt_mean[b], 1);
        s_last = (old == NCHUNK - 1);
    }
    __syncthreads();
    if (!s_last) return;
    __threadfence();

    const int w = t >> 5, lane = t & 31;
    float4 acc = make_float4(0.f, 0.f, 0.f, 0.f);
    #pragma unroll
    for (int z2 = 0; z2 < NCHUNK; z2++) {
        float4 p = reinterpret_cast<const float4*>(g_part)[((size_t)z2 * BB + b) * D4 + t];
        acc.x += p.x; acc.y += p.y; acc.z += p.z; acc.w += p.w;
    }
    const float inv = 1.0f / (float)NN;
    float4 v = make_float4(acc.x * inv, acc.y * inv, acc.z * inv, acc.w * inv);

    float ss = v.x * v.x + v.y * v.y + v.z * v.z + v.w * v.w;
    ss = warp_sum(ss);
    __shared__ float sm[6];
    __shared__ float s_rinv;
    if (lane == 0) sm[w] = ss;
    __syncthreads();
    if (t == 0) {
        float tot = 0.f;
        #pragma unroll
        for (int i = 0; i < 6; i++) tot += sm[i];
        s_rinv = 1.0f / sqrtf(fmaxf(tot, 1e-12f));
        g_cnt_mean[b] = 0;
    }
    __syncthreads();
    const float rinv = s_rinv;
    reinterpret_cast<float4*>(g_xnorm + (size_t)b * DIM)[t] =
        make_float4(v.x * rinv, v.y * rinv, v.z * rinv, v.w * rinv);
}

// ---------------------------------------------------------------------------
// sim pass: 16 prompts (pb) x 32 queries (bt); fused key-norm; per-block
// candidate written to cv/ci.
// ---------------------------------------------------------------------------
__device__ __forceinline__ void sim_pass(const float* __restrict__ keys,
                                         const float* __restrict__ qbase,
                                         float* __restrict__ cv, int* __restrict__ ci,
                                         float4* sq, int pb, int bt, int t) {
    const int w = t >> 5, lane = t & 31;

    for (int i = t; i < 32 * D4; i += 256) {
        const int r = i / D4, c = i % D4;
        sq[r * QSTR + c] =
            reinterpret_cast<const float4*>(qbase + (size_t)(bt * 32 + r) * DIM)[c];
    }
    __syncthreads();

    const int p0 = pb * 16 + w * 2;
    const float4* k0 = reinterpret_cast<const float4*>(keys + (size_t)p0 * DIM);
    const float4* k1 = k0 + D4;

    float s0 = 0.f, s1 = 0.f;
    #pragma unroll
    for (int jj = 0; jj < 6; jj++) {
        float4 a = k0[lane + 32 * jj];
        s0 += a.x * a.x + a.y * a.y + a.z * a.z + a.w * a.w;
        float4 c = k1[lane + 32 * jj];
        s1 += c.x * c.x + c.y * c.y + c.z * c.z + c.w * c.w;
    }
    s0 = warp_sum(s0); s1 = warp_sum(s1);
    const float r0 = 1.0f / sqrtf(fmaxf(s0, 1e-12f));
    const float r1 = 1.0f / sqrtf(fmaxf(s1, 1e-12f));

    const float4* q = sq + (size_t)lane * QSTR;
    float a0 = 0.f, a1 = 0.f, b0 = 0.f, b1 = 0.f;
    #pragma unroll 4
    for (int j = 0; j < D4; j++) {
        float4 ka = k0[j];
        float4 kb = k1[j];
        float4 qq = q[j];
        a0 += ka.x * qq.x + ka.y * qq.y;
        a1 += ka.z * qq.z + ka.w * qq.w;
        b0 += kb.x * qq.x + kb.y * qq.y;
        b1 += kb.z * qq.z + kb.w * qq.w;
    }
    const float v0 = r0 * (a0 + a1);
    const float v1 = r1 * (b0 + b1);

    float bv = v0; int bi = p0;
    if (v1 > v0) { bv = v1; bi = p0 + 1; }

    __shared__ float cvs[8][32];
    __shared__ int   cis[8][32];
    cvs[w][lane] = bv; cis[w][lane] = bi;
    __syncthreads();
    if (w == 0) {
        float best = cvs[0][lane]; int besti = cis[0][lane];
        #pragma unroll
        for (int i = 1; i < 8; i++) {
            float ov = cvs[i][lane]; int oi = cis[i][lane];
            if (ov > best || (ov == best && oi < besti)) { best = ov; besti = oi; }
        }
        const int b = bt * 32 + lane;
        cv[pb * BB + b] = best; ci[pb * BB + b] = besti;
    }
    __syncthreads();
}

// ---------------------------------------------------------------------------
// K2: the whole chain in one kernel. grid (PBLK, 2), 256 threads, 1 block/SM.
// ---------------------------------------------------------------------------
__global__ void k_chain(const float* __restrict__ pk,
                        const float* __restrict__ rpk,
                        const float* __restrict__ prompt,
                        const float* __restrict__ rprompt,
                        float* __restrict__ out,
                        long long out_size) {
    const int pb = blockIdx.x;
    const int bt = blockIdx.y;
    const int t = threadIdx.x;
    const int lane = t & 31;
    const int gid = bt * PBLK + pb;
    extern __shared__ float4 sq[];

    // Phase 1: level-1 sim
    sim_pass(pk, g_xnorm, g_c1v, g_c1i, sq, pb, bt, t);
    grid_bar(0);

    // Phase 2: blocks pb<32 reduce candidates for batch bt*32+pb, build resq
    if (pb < 32) {
        const int b = bt * 32 + pb;
        __shared__ int s_idx;
        if (t < 32) {
            float v; int i;
            reduce_cand(g_c1v, g_c1i, b, lane, v, i);
            if (lane == 0) { g_idx[b] = i; g_maxsim[b] = v; s_idx = i; }
        }
        __syncthreads();
        const int idx = s_idx;
        if (t < D4) {
            float4 a  = reinterpret_cast<const float4*>(pk + (size_t)idx * DIM)[t];
            float4 xn = reinterpret_cast<const float4*>(g_xnorm + (size_t)b * DIM)[t];
            reinterpret_cast<float4*>(g_resq + (size_t)b * DIM)[t] =
                make_float4(a.x - xn.x, a.y - xn.y, a.z - xn.z, a.w - xn.w);
        }
    }
    grid_bar(1);

    // Phase 3: level-2 sim (queries = residuals)
    sim_pass(rpk, g_resq, g_c2v, g_c2i, sq, pb, bt, t);
    grid_bar(2);

    // Phase 4: gather. 2 blocks per batch: half 0 -> rprompt, half 1 -> prompt
    {
        const int b = gid >> 1;
        const int half = gid & 1;
        __shared__ int s_ridx;
        if (t < 32) {
            float v; int i;
            reduce_cand(g_c2v, g_c2i, b, lane, v, i);
            if (lane == 0) s_ridx = i;
        }
        __syncthreads();
        const int SEG = LEN * DIM / 4;    // 3072
        float4* dst = reinterpret_cast<float4*>(out + (size_t)b * ROW * DIM);
        if (half == 0) {
            const float4* s1 = reinterpret_cast<const float4*>(
                rprompt + (size_t)s_ridx * LEN * DIM);
            #pragma unroll 4
            for (int i = t; i < SEG; i += 256) dst[i] = s1[i];
        } else {
            const float4* s2 = reinterpret_cast<const float4*>(
                prompt + (size_t)g_idx[b] * LEN * DIM);
            #pragma unroll 4
            for (int i = t; i < SEG; i += 256) dst[SEG + i] = s2[i];
        }

        // scalar loss on block gid==0
        if (gid == 0) {
            __shared__ float psum[64];
            if (t < 64) {
                float v = g_c2v[t]; int i = g_c2i[t];
                #pragma unroll 8
                for (int pbk = 1; pbk < PBLK; pbk++) {
                    float ov = g_c2v[pbk * BB + t]; int oi = g_c2i[pbk * BB + t];
                    if (ov > v || (ov == v && oi < i)) { v = ov; i = oi; }
                }
                psum[t] = g_maxsim[t] + v;
            }
            __syncthreads();
            if (t == 0) {
                float s = 0.f;
                #pragma unroll
                for (int i = 0; i < 64; i++) s += psum[i];
                s *= (1.0f / (float)BB);
                const size_t np = (size_t)BB * ROW * DIM;
                if ((size_t)out_size > np) out[(size_t)out_size - 1] = s;
            }
        }
    }

    // Exit barrier: last arriver resets all counters (nobody polls after this).
    __syncthreads();
    if (t == 0) {
        int old = atomicAdd(&g_bar[3], 1);
        if (old == CHAIN_BLOCKS - 1) {
            g_bar[0] = 0; g_bar[1] = 0; g_bar[2] = 0;
            __threadfence();
            g_bar[3] = 0;
        }
    }
}

// ---------------------------------------------------------------------------
extern "C" void kernel_launch(void* const* d_in, const int* in_sizes, int n_in,
                              void* d_out, int out_size) {
    const float* x       = (const float*)d_in[0];
    const float* prompt  = (const float*)d_in[1];
    const float* pk      = (const float*)d_in[2];
    const float* rprompt = (const float*)d_in[3];
    const float* rpk     = (const float*)d_in[4];
    float* out = (float*)d_out;

    const int SIM_SMEM = 32 * QSTR * 16;  // 98816 bytes
    static int attr_done = 0;
    if (!attr_done) {
        cudaFuncSetAttribute(k_chain, cudaFuncAttributeMaxDynamicSharedMemorySize, SIM_SMEM);
        attr_done = 1;
    }

    k_mean_copy<<<dim3(BB, NCHUNK), D4>>>(x, out);
    k_chain<<<dim3(PBLK, 2), 256, SIM_SMEM>>>(pk, rpk, prompt, rprompt,
                                              out, (long long)out_size);
}